// round 14
// baseline (speedup 1.0000x reference)
#include <cuda_runtime.h>
#include <cuda_fp16.h>
#include <cstdint>
#include <cstddef>
#include <cstring>

// TensorFusion via mma.sync fp16 2-term split — compute_103-safe.
// out1[b,h] = sum_i a_h[b,i] * (G[b,:] @ W1_i),  G[b,jk] = v_h[b,j]*t_h[b,k]
// G = Gh + Gl (fp16 hi/lo); terms Gh*Wh + Gl*Wh.
// W stored [h][k] in smem -> B fragments via NON-trans ldmatrix
// (kills the replay-heavy ldmatrix.trans that saturated L1 in rounds 8/11).
// 512 threads, 1 CTA/SM (regfile-bound), A (G) fragments register-resident.
// Grid 4 btiles x 67 jk-splits (KC=64) = 268 CTAs.

#define NSPLIT 67
#define KC 64
#define JK_TOTAL 4225
#define NI 65

__device__ float g_partial[NSPLIT * 512 * 64];
__device__ float g_h1[512 * 64];

// ---------- helpers ----------
__device__ __forceinline__ uint32_t smem_u32(const void* p) {
    uint32_t r;
    asm("{ .reg .u64 t; cvta.to.shared.u64 t, %1; cvt.u32.u64 %0, t; }" : "=r"(r) : "l"(p));
    return r;
}
__device__ __forceinline__ uint32_t h2u(half2 h) {
    uint32_t u;
    memcpy(&u, &h, 4);
    return u;
}
#define LDSM4(R, ADDR) \
    asm volatile("ldmatrix.sync.aligned.m8n8.x4.shared.b16 {%0,%1,%2,%3}, [%4];" \
                 : "=r"((R)[0]), "=r"((R)[1]), "=r"((R)[2]), "=r"((R)[3]) : "r"(ADDR))
#define MMA_F16(D, A, B0, B1) \
    asm volatile("mma.sync.aligned.m16n8k16.row.col.f32.f16.f16.f32 " \
                 "{%0,%1,%2,%3}, {%4,%5,%6,%7}, {%8,%9}, {%0,%1,%2,%3};" \
                 : "+f"((D)[0]), "+f"((D)[1]), "+f"((D)[2]), "+f"((D)[3]) \
                 : "r"((A)[0]), "r"((A)[1]), "r"((A)[2]), "r"((A)[3]), "r"(B0), "r"(B1))

// ---------- smem layout ----------
// W bufs: 2 x [64 h-rows][72 k cols] fp16 (stride 144B; n-major for non-trans LDSM)
// G tiles hi/lo: [128 b-rows][72 jk cols] fp16 (stride 144B)
#define W_KSTRIDE 72
#define WI_BYTES (64 * W_KSTRIDE * 2)           // 9216 per buffer
#define SM_WBUF  0                              // 2 bufs -> 18432
#define G_STRIDE 72
#define SM_GHI   (2 * WI_BYTES)                 // 18432
#define SM_GLO   (SM_GHI + 128 * G_STRIDE * 2)  // 36864
#define SMEM_TOTAL (SM_GLO + 128 * G_STRIDE * 2) // 55296

__global__ __launch_bounds__(512, 1)
void fusion_mma_kernel(const float* __restrict__ l, const float* __restrict__ a,
                       const float* __restrict__ v, const float* __restrict__ W1) {
    extern __shared__ __align__(1024) char smem[];
    const uint32_t sb = smem_u32(smem);
    const int tid  = threadIdx.x;
    const int warp = tid >> 5;
    const int lane = tid & 31;
    const int mw   = warp & 7;       // m-tile 0..7
    const int nh   = warp >> 3;      // n-half 0..1
    const int b0   = blockIdx.x * 128;
    const int jk0  = blockIdx.y * KC;

    // ---- build G tile [128][64] fp16 hi/lo ----
    {
        int r  = tid >> 2;
        int c0 = (tid & 3) * 16;
        const float* lrow = l + (size_t)(b0 + r) * 64;
        const float* vrow = v + (size_t)(b0 + r) * 64;
        int jk = jk0 + c0;
        int j  = jk / 65, k = jk - j * 65;
        char* gh = smem + SM_GHI + (size_t)(r * G_STRIDE + c0) * 2;
        char* gl = smem + SM_GLO + (size_t)(r * G_STRIDE + c0) * 2;
        #pragma unroll
        for (int c = 0; c < 16; c += 2) {
            float g0 = 0.0f, g1 = 0.0f;
            if (jk < JK_TOTAL)
                g0 = (j ? __ldg(&vrow[j - 1]) : 1.0f) * (k ? __ldg(&lrow[k - 1]) : 1.0f);
            ++jk; if (++k == 65) { k = 0; ++j; }
            if (jk < JK_TOTAL)
                g1 = (j ? __ldg(&vrow[j - 1]) : 1.0f) * (k ? __ldg(&lrow[k - 1]) : 1.0f);
            ++jk; if (++k == 65) { k = 0; ++j; }
            half2 hp = __floats2half2_rn(g0, g1);
            float2 hf = __half22float2(hp);
            half2 lp = __floats2half2_rn(g0 - hf.x, g1 - hf.y);
            *(half2*)(gh + c * 2) = hp;
            *(half2*)(gl + c * 2) = lp;
        }
    }

    // ---- W staging mapping: thread t -> h = t&63, k-range (t>>6)*8..+8 ----
    const int wr_h  = tid & 63;
    const int wr_k0 = (tid >> 6) * 8;
    const int kvalid = min(8, max(0, JK_TOTAL - jk0 - wr_k0));   // rows in-bounds
    const size_t w_sts_off = (size_t)(wr_h * W_KSTRIDE + wr_k0) * 2;

    float wpre[8];
    {   // LDG W for i=0
        const float* src = W1 + ((size_t)(jk0 + wr_k0)) * 64 + wr_h;
        #pragma unroll
        for (int kk = 0; kk < 8; ++kk)
            wpre[kk] = (kk < kvalid) ? __ldg(src + (size_t)kk * 64) : 0.0f;
    }
    {   // STS W i=0 into buf0
        uint4 pk;
        pk.x = h2u(__floats2half2_rn(wpre[0], wpre[1]));
        pk.y = h2u(__floats2half2_rn(wpre[2], wpre[3]));
        pk.z = h2u(__floats2half2_rn(wpre[4], wpre[5]));
        pk.w = h2u(__floats2half2_rn(wpre[6], wpre[7]));
        *(uint4*)(smem + SM_WBUF + w_sts_off) = pk;
    }
    __syncthreads();

    // ---- preload A (G) fragments into registers (i-invariant) ----
    uint32_t AH[4][4], AL[4][4];
    {
        const uint32_t a_row = (uint32_t)(mw * 16 + (lane & 7) + ((lane >> 3) & 1) * 8);
        const uint32_t a_off = a_row * (G_STRIDE * 2) + ((lane >> 4) & 1) * 16;
        #pragma unroll
        for (int ks = 0; ks < 4; ++ks) {
            LDSM4(AH[ks], sb + SM_GHI + a_off + (uint32_t)ks * 32);
            LDSM4(AL[ks], sb + SM_GLO + a_off + (uint32_t)ks * 32);
        }
    }

    // ---- non-trans B ldmatrix addressing ----
    const uint32_t b_n = (uint32_t)(nh * 32 + ((lane >> 4) & 1) * 8 + (lane & 7));  // h row
    const uint32_t b_k = (uint32_t)(((lane >> 3) & 1) * 8);                          // k offset
    const uint32_t b_off = b_n * (W_KSTRIDE * 2) + b_k * 2;

    float acc[4][4];
    #pragma unroll
    for (int nt = 0; nt < 4; ++nt)
        #pragma unroll
        for (int q = 0; q < 4; ++q) acc[nt][q] = 0.0f;

    const int arow0 = mw * 16 + (lane >> 2);
    const float* a_r0 = a + (size_t)(b0 + arow0) * 64;
    const float* a_r1 = a + (size_t)(b0 + arow0 + 8) * 64;

    for (int i = 0; i < NI; ++i) {
        // prefetch W[i+1]
        if (i + 1 < NI) {
            const float* src = W1 + ((size_t)(i + 1) * JK_TOTAL + jk0 + wr_k0) * 64 + wr_h;
            #pragma unroll
            for (int kk = 0; kk < 8; ++kk)
                wpre[kk] = (kk < kvalid) ? __ldg(src + (size_t)kk * 64) : 0.0f;
        }
        float av0 = (i == 0) ? 1.0f : __ldg(a_r0 + i - 1);
        float av1 = (i == 0) ? 1.0f : __ldg(a_r1 + i - 1);

        const uint32_t wb = sb + SM_WBUF + (uint32_t)(i & 1) * WI_BYTES + b_off;

        float d[4][4];
        #pragma unroll
        for (int nt = 0; nt < 4; ++nt)
            #pragma unroll
            for (int q = 0; q < 4; ++q) d[nt][q] = 0.0f;

        #pragma unroll
        for (int ks = 0; ks < 4; ++ks) {
            uint32_t bf[2][4];
            LDSM4(bf[0], wb + (uint32_t)ks * 32);                        // n 0..15 of half
            LDSM4(bf[1], wb + 16 * (W_KSTRIDE * 2) + (uint32_t)ks * 32); // n 16..31 of half
            #pragma unroll
            for (int nt = 0; nt < 4; ++nt) {
                const int g = nt >> 1, o = (nt & 1) * 2;
                MMA_F16(d[nt], AH[ks], bf[g][o], bf[g][o + 1]);
            }
            #pragma unroll
            for (int nt = 0; nt < 4; ++nt) {
                const int g = nt >> 1, o = (nt & 1) * 2;
                MMA_F16(d[nt], AL[ks], bf[g][o], bf[g][o + 1]);
            }
        }

        // scale by a_h and accumulate
        #pragma unroll
        for (int nt = 0; nt < 4; ++nt) {
            acc[nt][0] = fmaf(av0, d[nt][0], acc[nt][0]);
            acc[nt][1] = fmaf(av0, d[nt][1], acc[nt][1]);
            acc[nt][2] = fmaf(av1, d[nt][2], acc[nt][2]);
            acc[nt][3] = fmaf(av1, d[nt][3], acc[nt][3]);
        }

        // STS W[i+1] into other buffer
        if (i + 1 < NI) {
            uint4 pk;
            pk.x = h2u(__floats2half2_rn(wpre[0], wpre[1]));
            pk.y = h2u(__floats2half2_rn(wpre[2], wpre[3]));
            pk.z = h2u(__floats2half2_rn(wpre[4], wpre[5]));
            pk.w = h2u(__floats2half2_rn(wpre[6], wpre[7]));
            *(uint4*)(smem + SM_WBUF + (size_t)((i + 1) & 1) * WI_BYTES + w_sts_off) = pk;
        }
        __syncthreads();
    }

    // ---- write split partial ----
    {
        float* gp = g_partial + (size_t)blockIdx.y * (512 * 64) + (size_t)b0 * 64;
        const int c0 = nh * 32 + (lane & 3) * 2;
        #pragma unroll
        for (int nt = 0; nt < 4; ++nt) {
            *(float2*)(gp + (size_t)arow0 * 64 + nt * 8 + c0)       = make_float2(acc[nt][0], acc[nt][1]);
            *(float2*)(gp + (size_t)(arow0 + 8) * 64 + nt * 8 + c0) = make_float2(acc[nt][2], acc[nt][3]);
        }
    }
}

// ---------- reduce: sum 67 partials + b1 + tanh -> g_h1 ----------
__global__ __launch_bounds__(256, 1)
void reduce_kernel(const float* __restrict__ b1) {
    int idx = blockIdx.x * 256 + threadIdx.x;    // 0..32767
    float s0 = 0.f, s1 = 0.f;
    #pragma unroll
    for (int r = 0; r + 1 < NSPLIT; r += 2) {
        s0 += g_partial[(size_t)r * 32768 + idx];
        s1 += g_partial[(size_t)(r + 1) * 32768 + idx];
    }
    s0 += g_partial[(size_t)(NSPLIT - 1) * 32768 + idx];
    g_h1[idx] = tanhf(s0 + s1 + b1[idx & 63]);
}

// ---------- MLP layers 2,3 ----------
__global__ __launch_bounds__(256, 1)
void mlp_kernel(const float* __restrict__ W2, const float* __restrict__ b2,
                const float* __restrict__ W3, const float* __restrict__ b3,
                float* __restrict__ out) {
    __shared__ __align__(16) float h_s[64 * 65];
    __shared__ __align__(16) float w_s[64 * 64];
    const int tid = threadIdx.x;
    const int bt  = blockIdx.x;      // 0..7

    for (int x = tid; x < 4096; x += 256)
        h_s[(x >> 6) * 65 + (x & 63)] = g_h1[bt * 4096 + x];
    for (int x = tid; x < 1024; x += 256)
        ((float4*)w_s)[x] = ((const float4*)W2)[x];
    __syncthreads();

    const int hg = tid & 7, bg = tid >> 3;
    const int h0 = hg * 8;
    float acc[2][8];

    #pragma unroll
    for (int bb = 0; bb < 2; ++bb)
        #pragma unroll
        for (int hh = 0; hh < 8; ++hh) acc[bb][hh] = 0.0f;
    #pragma unroll 4
    for (int k = 0; k < 64; ++k) {
        float hv0 = h_s[(bg * 2 + 0) * 65 + k];
        float hv1 = h_s[(bg * 2 + 1) * 65 + k];
        const float* wr = &w_s[k * 64 + h0];
        #pragma unroll
        for (int hh = 0; hh < 8; ++hh) {
            float wv = wr[hh];
            acc[0][hh] += hv0 * wv;
            acc[1][hh] += hv1 * wv;
        }
    }
    __syncthreads();
    #pragma unroll
    for (int bb = 0; bb < 2; ++bb)
        #pragma unroll
        for (int hh = 0; hh < 8; ++hh)
            h_s[(bg * 2 + bb) * 65 + h0 + hh] = tanhf(acc[bb][hh] + b2[h0 + hh]);
    for (int x = tid; x < 1024; x += 256)
        ((float4*)w_s)[x] = ((const float4*)W3)[x];
    __syncthreads();

    #pragma unroll
    for (int bb = 0; bb < 2; ++bb)
        #pragma unroll
        for (int hh = 0; hh < 8; ++hh) acc[bb][hh] = 0.0f;
    #pragma unroll 4
    for (int k = 0; k < 64; ++k) {
        float hv0 = h_s[(bg * 2 + 0) * 65 + k];
        float hv1 = h_s[(bg * 2 + 1) * 65 + k];
        const float* wr = &w_s[k * 64 + h0];
        #pragma unroll
        for (int hh = 0; hh < 8; ++hh) {
            float wv = wr[hh];
            acc[0][hh] += hv0 * wv;
            acc[1][hh] += hv1 * wv;
        }
    }
    #pragma unroll
    for (int bb = 0; bb < 2; ++bb) {
        int b = bt * 64 + bg * 2 + bb;
        float o[8];
        #pragma unroll
        for (int hh = 0; hh < 8; ++hh)
            o[hh] = tanhf(acc[bb][hh] + b3[h0 + hh]);
        *(float4*)(&out[b * 64 + h0])     = make_float4(o[0], o[1], o[2], o[3]);
        *(float4*)(&out[b * 64 + h0 + 4]) = make_float4(o[4], o[5], o[6], o[7]);
    }
}

extern "C" void kernel_launch(void* const* d_in, const int* in_sizes, int n_in,
                              void* d_out, int out_size) {
    (void)in_sizes; (void)n_in; (void)out_size;
    const float* l  = (const float*)d_in[0];
    const float* a  = (const float*)d_in[1];
    const float* v  = (const float*)d_in[2];
    const float* W1 = (const float*)d_in[3];
    const float* b1 = (const float*)d_in[4];
    const float* W2 = (const float*)d_in[5];
    const float* b2 = (const float*)d_in[6];
    const float* W3 = (const float*)d_in[7];
    const float* b3 = (const float*)d_in[8];
    float* out = (float*)d_out;

    cudaFuncSetAttribute(fusion_mma_kernel,
                         cudaFuncAttributeMaxDynamicSharedMemorySize, SMEM_TOTAL);
    dim3 grid1(4, NSPLIT);
    fusion_mma_kernel<<<grid1, 512, SMEM_TOTAL>>>(l, a, v, W1);
    reduce_kernel<<<128, 256>>>(b1);
    mlp_kernel<<<8, 256>>>(W2, b2, W3, b3, out);
}

// round 16
// speedup vs baseline: 1.3616x; 1.3616x over previous
#include <cuda_runtime.h>
#include <cuda_fp16.h>
#include <cstdint>
#include <cstddef>
#include <cstring>

// TensorFusion via mma.sync fp16 SINGLE-term — compute_103-safe.
// out1[b,h] = sum_i a_h[b,i] * (G[b,:] @ W1_i),  G[b,jk] = v_h[b,j]*t_h[b,k]
// Gh*Wh only. Evidence: 2-term rel_err 2.35e-4 was purely W-rounding;
// adding G-rounding of same scale -> ~3.3e-4, still < 1e-3. Halves MMA work.
// Base schedule = round-8 best (512 thr, trans-LDSM B, float4 W LDG, a_s staged).
// Grid 4 btiles x 67 jk-splits (KC=64) = 268 CTAs.

#define NSPLIT 67
#define KC 64
#define JK_TOTAL 4225
#define NI 65

__device__ float g_partial[NSPLIT * 512 * 64];
__device__ float g_h1[512 * 64];

// ---------- helpers ----------
__device__ __forceinline__ uint32_t smem_u32(const void* p) {
    uint32_t r;
    asm("{ .reg .u64 t; cvta.to.shared.u64 t, %1; cvt.u32.u64 %0, t; }" : "=r"(r) : "l"(p));
    return r;
}
__device__ __forceinline__ uint32_t h2u(half2 h) {
    uint32_t u;
    memcpy(&u, &h, 4);
    return u;
}
#define LDSM4(R, ADDR) \
    asm volatile("ldmatrix.sync.aligned.m8n8.x4.shared.b16 {%0,%1,%2,%3}, [%4];" \
                 : "=r"((R)[0]), "=r"((R)[1]), "=r"((R)[2]), "=r"((R)[3]) : "r"(ADDR))
#define LDSM4T(R, ADDR) \
    asm volatile("ldmatrix.sync.aligned.m8n8.x4.trans.shared.b16 {%0,%1,%2,%3}, [%4];" \
                 : "=r"((R)[0]), "=r"((R)[1]), "=r"((R)[2]), "=r"((R)[3]) : "r"(ADDR))
#define MMA_F16(D, A, B0, B1) \
    asm volatile("mma.sync.aligned.m16n8k16.row.col.f32.f16.f16.f32 " \
                 "{%0,%1,%2,%3}, {%4,%5,%6,%7}, {%8,%9}, {%0,%1,%2,%3};" \
                 : "+f"((D)[0]), "+f"((D)[1]), "+f"((D)[2]), "+f"((D)[3]) \
                 : "r"((A)[0]), "r"((A)[1]), "r"((A)[2]), "r"((A)[3]), "r"(B0), "r"(B1))

// ---------- smem layout ----------
// W bufs (fp16): 2 x [64 rows(k)][72 cols(h)]  stride 144B (conflict-free)
// G tile (fp16 hi): [128 rows(b)][72 cols(jk)] stride 144B
// a_s: [128][65] f32
#define W_STRIDE 72
#define W_BYTES  (64 * W_STRIDE * 2)            // 9216
#define SM_WBUF  0                              // 2 bufs -> 18432
#define G_STRIDE 72
#define SM_GHI   (2 * W_BYTES)                  // 18432
#define SM_AS    (SM_GHI + 128 * G_STRIDE * 2)  // 36864
#define SMEM_TOTAL (SM_AS + 128 * 65 * 4)       // 70144

__global__ __launch_bounds__(512, 1)
void fusion_mma_kernel(const float* __restrict__ l, const float* __restrict__ a,
                       const float* __restrict__ v, const float* __restrict__ W1) {
    extern __shared__ __align__(1024) char smem[];
    const uint32_t sb = smem_u32(smem);
    const int tid  = threadIdx.x;
    const int warp = tid >> 5;
    const int lane = tid & 31;
    const int mw   = warp & 7;       // m-tile 0..7
    const int nh   = warp >> 3;      // n-half 0..1
    const int b0   = blockIdx.x * 128;
    const int jk0  = blockIdx.y * KC;

    float* a_s = (float*)(smem + SM_AS);

    // ---- stage a_s[128][65] ----
    for (int x = tid; x < 128 * 65; x += 512) {
        int r = x / 65, i = x - r * 65;
        a_s[x] = (i == 0) ? 1.0f : __ldg(&a[(b0 + r) * 64 + (i - 1)]);
    }

    // ---- build G tile [128][64] fp16 (hi only) ----
    {
        int r  = tid >> 2;
        int c0 = (tid & 3) * 16;
        const float* lrow = l + (size_t)(b0 + r) * 64;
        const float* vrow = v + (size_t)(b0 + r) * 64;
        int jk = jk0 + c0;
        int j  = jk / 65, k = jk - j * 65;
        char* gh = smem + SM_GHI + (size_t)(r * G_STRIDE + c0) * 2;
        #pragma unroll
        for (int c = 0; c < 16; c += 2) {
            float g0 = 0.0f, g1 = 0.0f;
            if (jk < JK_TOTAL)
                g0 = (j ? __ldg(&vrow[j - 1]) : 1.0f) * (k ? __ldg(&lrow[k - 1]) : 1.0f);
            ++jk; if (++k == 65) { k = 0; ++j; }
            if (jk < JK_TOTAL)
                g1 = (j ? __ldg(&vrow[j - 1]) : 1.0f) * (k ? __ldg(&lrow[k - 1]) : 1.0f);
            ++jk; if (++k == 65) { k = 0; ++j; }
            *(half2*)(gh + c * 2) = __floats2half2_rn(g0, g1);
        }
    }

    // ---- W staging mapping: thread t -> row t>>3 (k), cols (t&7)*8..+8 ----
    const int wr_row = tid >> 3;                 // 0..63
    const int wr_c0  = (tid & 7) * 8;
    const bool wrow_ok = (jk0 + wr_row) < JK_TOTAL;

    float4 wreg[2];
    {   // LDG W for i=0
        const float4* src = (const float4*)(W1 + ((size_t)0 * JK_TOTAL + jk0 + wr_row) * 64 + wr_c0);
        wreg[0] = wrow_ok ? __ldg(src)     : make_float4(0.f, 0.f, 0.f, 0.f);
        wreg[1] = wrow_ok ? __ldg(src + 1) : make_float4(0.f, 0.f, 0.f, 0.f);
    }
    {   // STS W i=0 into buf0
        uint4 pk;
        pk.x = h2u(__floats2half2_rn(wreg[0].x, wreg[0].y));
        pk.y = h2u(__floats2half2_rn(wreg[0].z, wreg[0].w));
        pk.z = h2u(__floats2half2_rn(wreg[1].x, wreg[1].y));
        pk.w = h2u(__floats2half2_rn(wreg[1].z, wreg[1].w));
        *(uint4*)(smem + SM_WBUF + (size_t)(wr_row * W_STRIDE + wr_c0) * 2) = pk;
    }
    __syncthreads();

    // ---- preload A (G) fragments into registers: i-invariant ----
    uint32_t AH[4][4];
    {
        const uint32_t a_row = (uint32_t)(mw * 16 + (lane & 7) + ((lane >> 3) & 1) * 8);
        const uint32_t a_off = a_row * (G_STRIDE * 2) + ((lane >> 4) & 1) * 16;
        #pragma unroll
        for (int ks = 0; ks < 4; ++ks)
            LDSM4(AH[ks], sb + SM_GHI + a_off + (uint32_t)ks * 32);
    }

    // B address components (trans ldmatrix, K-major W)
    const uint32_t b_row  = (uint32_t)((lane & 7) + ((lane >> 3) & 1) * 8);
    const uint32_t b_colb = (uint32_t)(nh * 64 + ((lane >> 4) & 1) * 16);  // bytes

    float acc[4][4];
    #pragma unroll
    for (int nt = 0; nt < 4; ++nt)
        #pragma unroll
        for (int q = 0; q < 4; ++q) acc[nt][q] = 0.0f;

    const int arow0 = mw * 16 + (lane >> 2);

    for (int i = 0; i < NI; ++i) {
        // prefetch W[i+1]
        if (i + 1 < NI) {
            const float4* src = (const float4*)(W1 + ((size_t)(i + 1) * JK_TOTAL + jk0 + wr_row) * 64 + wr_c0);
            wreg[0] = wrow_ok ? __ldg(src)     : make_float4(0.f, 0.f, 0.f, 0.f);
            wreg[1] = wrow_ok ? __ldg(src + 1) : make_float4(0.f, 0.f, 0.f, 0.f);
        }
        float av0 = a_s[arow0 * 65 + i];
        float av1 = a_s[(arow0 + 8) * 65 + i];

        const uint32_t wb = sb + SM_WBUF + (uint32_t)(i & 1) * W_BYTES;

        float d[4][4];
        #pragma unroll
        for (int nt = 0; nt < 4; ++nt)
            #pragma unroll
            for (int q = 0; q < 4; ++q) d[nt][q] = 0.0f;

        #pragma unroll
        for (int ks = 0; ks < 4; ++ks) {
            uint32_t bh[2][4];
            uint32_t roff = ((uint32_t)ks * 16 + b_row) * (W_STRIDE * 2);
            LDSM4T(bh[0], wb + roff + b_colb);
            LDSM4T(bh[1], wb + roff + 32 + b_colb);
            #pragma unroll
            for (int nt = 0; nt < 4; ++nt) {
                const int g = nt >> 1, o = (nt & 1) * 2;
                MMA_F16(d[nt], AH[ks], bh[g][o], bh[g][o + 1]);
            }
        }

        // scale by a_h and accumulate
        #pragma unroll
        for (int nt = 0; nt < 4; ++nt) {
            acc[nt][0] = fmaf(av0, d[nt][0], acc[nt][0]);
            acc[nt][1] = fmaf(av0, d[nt][1], acc[nt][1]);
            acc[nt][2] = fmaf(av1, d[nt][2], acc[nt][2]);
            acc[nt][3] = fmaf(av1, d[nt][3], acc[nt][3]);
        }

        // store W[i+1] into other buffer
        if (i + 1 < NI) {
            uint4 pk;
            pk.x = h2u(__floats2half2_rn(wreg[0].x, wreg[0].y));
            pk.y = h2u(__floats2half2_rn(wreg[0].z, wreg[0].w));
            pk.z = h2u(__floats2half2_rn(wreg[1].x, wreg[1].y));
            pk.w = h2u(__floats2half2_rn(wreg[1].z, wreg[1].w));
            *(uint4*)(smem + SM_WBUF + (size_t)((i + 1) & 1) * W_BYTES
                      + (size_t)(wr_row * W_STRIDE + wr_c0) * 2) = pk;
        }
        __syncthreads();
    }

    // ---- write split partial ----
    {
        float* gp = g_partial + (size_t)blockIdx.y * (512 * 64) + (size_t)b0 * 64;
        const int c0 = nh * 32 + (lane & 3) * 2;
        #pragma unroll
        for (int nt = 0; nt < 4; ++nt) {
            *(float2*)(gp + (size_t)arow0 * 64 + nt * 8 + c0)       = make_float2(acc[nt][0], acc[nt][1]);
            *(float2*)(gp + (size_t)(arow0 + 8) * 64 + nt * 8 + c0) = make_float2(acc[nt][2], acc[nt][3]);
        }
    }
}

// ---------- reduce: sum 67 partials + b1 + tanh -> g_h1 ----------
__global__ __launch_bounds__(256, 1)
void reduce_kernel(const float* __restrict__ b1) {
    int idx = blockIdx.x * 256 + threadIdx.x;    // 0..32767
    float s0 = 0.f, s1 = 0.f;
    #pragma unroll
    for (int r = 0; r + 1 < NSPLIT; r += 2) {
        s0 += g_partial[(size_t)r * 32768 + idx];
        s1 += g_partial[(size_t)(r + 1) * 32768 + idx];
    }
    s0 += g_partial[(size_t)(NSPLIT - 1) * 32768 + idx];
    g_h1[idx] = tanhf(s0 + s1 + b1[idx & 63]);
}

// ---------- MLP layers 2,3 ----------
__global__ __launch_bounds__(256, 1)
void mlp_kernel(const float* __restrict__ W2, const float* __restrict__ b2,
                const float* __restrict__ W3, const float* __restrict__ b3,
                float* __restrict__ out) {
    __shared__ __align__(16) float h_s[64 * 65];
    __shared__ __align__(16) float w_s[64 * 64];
    const int tid = threadIdx.x;
    const int bt  = blockIdx.x;      // 0..7

    for (int x = tid; x < 4096; x += 256)
        h_s[(x >> 6) * 65 + (x & 63)] = g_h1[bt * 4096 + x];
    for (int x = tid; x < 1024; x += 256)
        ((float4*)w_s)[x] = ((const float4*)W2)[x];
    __syncthreads();

    const int hg = tid & 7, bg = tid >> 3;
    const int h0 = hg * 8;
    float acc[2][8];

    #pragma unroll
    for (int bb = 0; bb < 2; ++bb)
        #pragma unroll
        for (int hh = 0; hh < 8; ++hh) acc[bb][hh] = 0.0f;
    #pragma unroll 4
    for (int k = 0; k < 64; ++k) {
        float hv0 = h_s[(bg * 2 + 0) * 65 + k];
        float hv1 = h_s[(bg * 2 + 1) * 65 + k];
        const float* wr = &w_s[k * 64 + h0];
        #pragma unroll
        for (int hh = 0; hh < 8; ++hh) {
            float wv = wr[hh];
            acc[0][hh] += hv0 * wv;
            acc[1][hh] += hv1 * wv;
        }
    }
    __syncthreads();
    #pragma unroll
    for (int bb = 0; bb < 2; ++bb)
        #pragma unroll
        for (int hh = 0; hh < 8; ++hh)
            h_s[(bg * 2 + bb) * 65 + h0 + hh] = tanhf(acc[bb][hh] + b2[h0 + hh]);
    for (int x = tid; x < 1024; x += 256)
        ((float4*)w_s)[x] = ((const float4*)W3)[x];
    __syncthreads();

    #pragma unroll
    for (int bb = 0; bb < 2; ++bb)
        #pragma unroll
        for (int hh = 0; hh < 8; ++hh) acc[bb][hh] = 0.0f;
    #pragma unroll 4
    for (int k = 0; k < 64; ++k) {
        float hv0 = h_s[(bg * 2 + 0) * 65 + k];
        float hv1 = h_s[(bg * 2 + 1) * 65 + k];
        const float* wr = &w_s[k * 64 + h0];
        #pragma unroll
        for (int hh = 0; hh < 8; ++hh) {
            float wv = wr[hh];
            acc[0][hh] += hv0 * wv;
            acc[1][hh] += hv1 * wv;
        }
    }
    #pragma unroll
    for (int bb = 0; bb < 2; ++bb) {
        int b = bt * 64 + bg * 2 + bb;
        float o[8];
        #pragma unroll
        for (int hh = 0; hh < 8; ++hh)
            o[hh] = tanhf(acc[bb][hh] + b3[h0 + hh]);
        *(float4*)(&out[b * 64 + h0])     = make_float4(o[0], o[1], o[2], o[3]);
        *(float4*)(&out[b * 64 + h0 + 4]) = make_float4(o[4], o[5], o[6], o[7]);
    }
}

extern "C" void kernel_launch(void* const* d_in, const int* in_sizes, int n_in,
                              void* d_out, int out_size) {
    (void)in_sizes; (void)n_in; (void)out_size;
    const float* l  = (const float*)d_in[0];
    const float* a  = (const float*)d_in[1];
    const float* v  = (const float*)d_in[2];
    const float* W1 = (const float*)d_in[3];
    const float* b1 = (const float*)d_in[4];
    const float* W2 = (const float*)d_in[5];
    const float* b2 = (const float*)d_in[6];
    const float* W3 = (const float*)d_in[7];
    const float* b3 = (const float*)d_in[8];
    float* out = (float*)d_out;

    cudaFuncSetAttribute(fusion_mma_kernel,
                         cudaFuncAttributeMaxDynamicSharedMemorySize, SMEM_TOTAL);
    dim3 grid1(4, NSPLIT);
    fusion_mma_kernel<<<grid1, 512, SMEM_TOTAL>>>(l, a, v, W1);
    reduce_kernel<<<128, 256>>>(b1);
    mlp_kernel<<<8, 256>>>(W2, b2, W3, b3, out);
}